// round 5
// baseline (speedup 1.0000x reference)
#include <cuda_runtime.h>
#include <cuda_bf16.h>

// PerfectSpatialHash:
//   oidx = trunc(coords_f * m1) mod 64       -> offsets = offset_table[oidx]  (3MB, L2-resident)
//   hidx = (trunc(coords_f * m0) + offsets) mod 256
//   out  = hash_table[hidx]                  (512MB, random 32B gathers)
//
// mod 2^k implemented as & (2^k - 1): exact floored-mod for any sign.

#define OFF_MASK  63
#define HASH_MASK 255

__global__ __launch_bounds__(256, 8)
void psh_kernel(const int*    __restrict__ coords,       // [N,3]
                const float4* __restrict__ hash_table,   // [256^3][2] float4
                const int*    __restrict__ offset_table, // [64^3,3]
                const float*  __restrict__ m0,
                const float*  __restrict__ m1,
                float4*       __restrict__ out,          // [N][2] float4
                int n)
{
    int i = blockIdx.x * blockDim.x + threadIdx.x;
    if (i >= n) return;

    // coords: 3 coalesced scalar loads (stride-12 arrays; warp covers 3 full lines)
    const int* cp = coords + 3ll * i;
    int c0 = __ldg(cp + 0);
    int c1 = __ldg(cp + 1);
    int c2 = __ldg(cp + 2);

    float f0 = (float)c0, f1 = (float)c1, f2 = (float)c2;

    // m0/m1 broadcast loads — L1-hit after first warp
    float m10 = __ldg(m1 + 0), m11 = __ldg(m1 + 1), m12 = __ldg(m1 + 2);
    float m00 = __ldg(m0 + 0), m01 = __ldg(m0 + 1), m02 = __ldg(m0 + 2);

    // offset-table index (trunc-toward-zero cast, floored-mod via mask)
    int o0 = ((int)(f0 * m10)) & OFF_MASK;
    int o1 = ((int)(f1 * m11)) & OFF_MASK;
    int o2 = ((int)(f2 * m12)) & OFF_MASK;

    int oi = ((o0 << 6) + o1) * 64 + o2;           // < 64^3
    const int* op = offset_table + 3 * oi;
    int t0 = __ldg(op + 0);
    int t1 = __ldg(op + 1);
    int t2 = __ldg(op + 2);

    // hash index
    int h0 = (((int)(f0 * m00)) + t0) & HASH_MASK;
    int h1 = (((int)(f1 * m01)) + t1) & HASH_MASK;
    int h2 = (((int)(f2 * m02)) + t2) & HASH_MASK;

    size_t hi = (((size_t)h0 << 8 | (unsigned)h1) << 8) | (unsigned)h2;  // row index into 256^3

    // 32B gather: two aligned LDG.128 from the same sector pair
    float4 a = __ldg(hash_table + 2 * hi + 0);
    float4 b = __ldg(hash_table + 2 * hi + 1);

    // 32B coalesced store
    size_t oidx = 2 * (size_t)i;
    out[oidx + 0] = a;
    out[oidx + 1] = b;
}

extern "C" void kernel_launch(void* const* d_in, const int* in_sizes, int n_in,
                              void* d_out, int out_size)
{
    const int*    coords       = (const int*)d_in[0];
    const float4* hash_table   = (const float4*)d_in[1];
    const int*    offset_table = (const int*)d_in[2];
    const float*  m0           = (const float*)d_in[3];
    const float*  m1           = (const float*)d_in[4];
    float4*       out          = (float4*)d_out;

    int n = in_sizes[0] / 3;   // N_QUERIES
    int threads = 256;
    int blocks  = (n + threads - 1) / threads;
    psh_kernel<<<blocks, threads>>>(coords, hash_table, offset_table, m0, m1, out, n);
}

// round 6
// speedup vs baseline: 1.3596x; 1.3596x over previous
#include <cuda_runtime.h>
#include <cuda_bf16.h>

// PerfectSpatialHash, round 5:
//  Pass 1: pack offset_table[64^3,3] int32 -> g_packed[64^3] uint (t&255 per byte).
//          (t mod 256) is all the downstream math needs; 1MB stays L2-resident.
//  Pass 2: per query: oidx -> one 4B gather from g_packed; hidx -> one 256-bit
//          gather (ld.global.nc.v8.b32, 32B-aligned rows); one 256-bit .cs store.

#define OFF_N  (64 * 64 * 64)

__device__ unsigned g_packed[OFF_N];   // 1 MB scratch (static: allocation-free)

__global__ void pack_offsets_kernel(const int* __restrict__ off)
{
    int i = blockIdx.x * blockDim.x + threadIdx.x;
    if (i >= OFF_N) return;
    const int* p = off + 3 * i;
    unsigned t0 = (unsigned)p[0] & 255u;
    unsigned t1 = (unsigned)p[1] & 255u;
    unsigned t2 = (unsigned)p[2] & 255u;
    g_packed[i] = t0 | (t1 << 8) | (t2 << 16);
}

__global__ __launch_bounds__(256, 8)
void psh_kernel(const int*   __restrict__ coords,      // [N,3]
                const float* __restrict__ hash_table,  // [256^3 * 8] floats, rows 32B-aligned
                const float* __restrict__ m0,
                const float* __restrict__ m1,
                float*       __restrict__ out,         // [N * 8] floats, rows 32B-aligned
                int n)
{
    int i = blockIdx.x * blockDim.x + threadIdx.x;
    if (i >= n) return;

    // coords: 3 coalesced scalar loads
    const int* cp = coords + 3ll * i;
    float f0 = (float)__ldg(cp + 0);
    float f1 = (float)__ldg(cp + 1);
    float f2 = (float)__ldg(cp + 2);

    // m0/m1 broadcast loads (L1-hit after first warp)
    float m10 = __ldg(m1 + 0), m11 = __ldg(m1 + 1), m12 = __ldg(m1 + 2);
    float m00 = __ldg(m0 + 0), m01 = __ldg(m0 + 1), m02 = __ldg(m0 + 2);

    // offset-table index (trunc-toward-zero cast; & 63 == floored mod 64)
    int o0 = ((int)(f0 * m10)) & 63;
    int o1 = ((int)(f1 * m11)) & 63;
    int o2 = ((int)(f2 * m12)) & 63;
    int oi = ((o0 << 6) + o1) * 64 + o2;

    // single 4B gather instead of 3 scalar gathers (L2-resident 1MB table)
    unsigned pk = __ldg(g_packed + oi);

    // hash index: (trunc(c*m0) + t) & 255 — exact floored-mod-256 arithmetic
    int h0 = (((int)(f0 * m00)) + (int)( pk        & 255u)) & 255;
    int h1 = (((int)(f1 * m01)) + (int)((pk >> 8)  & 255u)) & 255;
    int h2 = (((int)(f2 * m02)) + (int)((pk >> 16) & 255u)) & 255;

    size_t hi = ((((size_t)h0 << 8) | (unsigned)h1) << 8) | (unsigned)h2;

    // one 256-bit gather (row is 32B-aligned: base + 32*hi)
    const float* src = hash_table + 8 * hi;
    unsigned r0, r1, r2, r3, r4, r5, r6, r7;
    asm volatile(
        "ld.global.nc.v8.b32 {%0,%1,%2,%3,%4,%5,%6,%7}, [%8];"
        : "=r"(r0), "=r"(r1), "=r"(r2), "=r"(r3),
          "=r"(r4), "=r"(r5), "=r"(r6), "=r"(r7)
        : "l"(src));

    // one 256-bit streaming store (evict-first: keep L2 for gathers)
    float* dst = out + 8ll * i;
    asm volatile(
        "st.global.cs.v8.b32 [%8], {%0,%1,%2,%3,%4,%5,%6,%7};"
        :: "r"(r0), "r"(r1), "r"(r2), "r"(r3),
           "r"(r4), "r"(r5), "r"(r6), "r"(r7),
           "l"(dst)
        : "memory");
}

extern "C" void kernel_launch(void* const* d_in, const int* in_sizes, int n_in,
                              void* d_out, int out_size)
{
    const int*   coords       = (const int*)d_in[0];
    const float* hash_table   = (const float*)d_in[1];
    const int*   offset_table = (const int*)d_in[2];
    const float* m0           = (const float*)d_in[3];
    const float* m1           = (const float*)d_in[4];
    float*       out          = (float*)d_out;

    int n = in_sizes[0] / 3;   // N_QUERIES

    pack_offsets_kernel<<<(OFF_N + 255) / 256, 256>>>(offset_table);
    psh_kernel<<<(n + 255) / 256, 256>>>(coords, hash_table, m0, m1, out, n);
}

// round 7
// speedup vs baseline: 1.3908x; 1.0230x over previous
#include <cuda_runtime.h>
#include <cuda_bf16.h>

// PerfectSpatialHash, round 6:
//  Pass 1: pack offset_table[64^3,3] int32 -> g_packed[64^3] uint (t&255 per byte).
//  Pass 2: 4 queries per thread for MLP=4 on the DRAM hash gathers.
//          coords: 3x int4 evict-first loads (48B/thread, 16B-aligned).
//          offsets: 4 independent 4B gathers from L2-resident 1MB table.
//          hash:    4 independent 256-bit gathers (32B-aligned rows).
//          out:     4x 256-bit evict-first stores.

#define OFF_N  (64 * 64 * 64)
#define QPT    4

__device__ unsigned g_packed[OFF_N];   // 1 MB scratch (static: allocation-free)

__global__ void pack_offsets_kernel(const int* __restrict__ off)
{
    int i = blockIdx.x * blockDim.x + threadIdx.x;
    if (i >= OFF_N) return;
    const int* p = off + 3 * i;
    unsigned t0 = (unsigned)p[0] & 255u;
    unsigned t1 = (unsigned)p[1] & 255u;
    unsigned t2 = (unsigned)p[2] & 255u;
    g_packed[i] = t0 | (t1 << 8) | (t2 << 16);
}

__global__ __launch_bounds__(256)
void psh_kernel(const int*   __restrict__ coords,      // [N,3]
                const float* __restrict__ hash_table,  // [256^3 * 8] floats, rows 32B-aligned
                const float* __restrict__ m0,
                const float* __restrict__ m1,
                float*       __restrict__ out,         // [N * 8] floats, rows 32B-aligned
                int n)
{
    long long t    = (long long)blockIdx.x * blockDim.x + threadIdx.x;
    long long base = t * QPT;
    if (base >= n) return;
    int cnt = (int)((n - base < QPT) ? (n - base) : QPT);

    // m broadcasts (L1-hit after first warp)
    float m10 = __ldg(m1 + 0), m11 = __ldg(m1 + 1), m12 = __ldg(m1 + 2);
    float m00 = __ldg(m0 + 0), m01 = __ldg(m0 + 1), m02 = __ldg(m0 + 2);

    // ---- coords: 48B per thread, 16B-aligned -> 3x int4, evict-first ----
    int c[QPT][3];
    if (cnt == QPT) {
        const int4* cp = (const int4*)(coords + 3 * base);
        int4 A = __ldcs(cp + 0);
        int4 B = __ldcs(cp + 1);
        int4 C = __ldcs(cp + 2);
        c[0][0] = A.x; c[0][1] = A.y; c[0][2] = A.z;
        c[1][0] = A.w; c[1][1] = B.x; c[1][2] = B.y;
        c[2][0] = B.z; c[2][1] = B.w; c[2][2] = C.x;
        c[3][0] = C.y; c[3][1] = C.z; c[3][2] = C.w;
    } else {
        #pragma unroll
        for (int q = 0; q < QPT; q++) {
            if (q < cnt) {
                const int* p = coords + 3 * (base + q);
                c[q][0] = p[0]; c[q][1] = p[1]; c[q][2] = p[2];
            } else {
                c[q][0] = c[q][1] = c[q][2] = 0;
            }
        }
    }

    // ---- offset gathers: 4 independent 4B loads from L2-resident table ----
    float f[QPT][3];
    unsigned pk[QPT];
    #pragma unroll
    for (int q = 0; q < QPT; q++) {
        f[q][0] = (float)c[q][0];
        f[q][1] = (float)c[q][1];
        f[q][2] = (float)c[q][2];
        int o0 = ((int)(f[q][0] * m10)) & 63;   // trunc cast; &63 == floored mod 64
        int o1 = ((int)(f[q][1] * m11)) & 63;
        int o2 = ((int)(f[q][2] * m12)) & 63;
        int oi = ((o0 << 6) + o1) * 64 + o2;
        pk[q] = __ldg(g_packed + oi);           // safe even for padded lanes (oi in range)
    }

    // ---- hash gathers: 4 independent 256-bit loads ----
    const float* src[QPT];
    #pragma unroll
    for (int q = 0; q < QPT; q++) {
        int h0 = (((int)(f[q][0] * m00)) + (int)( pk[q]        & 255u)) & 255;
        int h1 = (((int)(f[q][1] * m01)) + (int)((pk[q] >> 8)  & 255u)) & 255;
        int h2 = (((int)(f[q][2] * m02)) + (int)((pk[q] >> 16) & 255u)) & 255;
        size_t hi = ((((size_t)h0 << 8) | (unsigned)h1) << 8) | (unsigned)h2;
        src[q] = hash_table + 8 * hi;
    }

    unsigned r[QPT][8];
    #pragma unroll
    for (int q = 0; q < QPT; q++) {
        if (q < cnt) {
            asm volatile(
                "ld.global.nc.v8.b32 {%0,%1,%2,%3,%4,%5,%6,%7}, [%8];"
                : "=r"(r[q][0]), "=r"(r[q][1]), "=r"(r[q][2]), "=r"(r[q][3]),
                  "=r"(r[q][4]), "=r"(r[q][5]), "=r"(r[q][6]), "=r"(r[q][7])
                : "l"(src[q]));
        }
    }

    // ---- stores: 4x 256-bit, evict-first (fully coalesced across the warp) ----
    #pragma unroll
    for (int q = 0; q < QPT; q++) {
        if (q < cnt) {
            float* dst = out + 8 * (base + q);
            asm volatile(
                "st.global.cs.v8.b32 [%8], {%0,%1,%2,%3,%4,%5,%6,%7};"
                :: "r"(r[q][0]), "r"(r[q][1]), "r"(r[q][2]), "r"(r[q][3]),
                   "r"(r[q][4]), "r"(r[q][5]), "r"(r[q][6]), "r"(r[q][7]),
                   "l"(dst)
                : "memory");
        }
    }
}

extern "C" void kernel_launch(void* const* d_in, const int* in_sizes, int n_in,
                              void* d_out, int out_size)
{
    const int*   coords       = (const int*)d_in[0];
    const float* hash_table   = (const float*)d_in[1];
    const int*   offset_table = (const int*)d_in[2];
    const float* m0           = (const float*)d_in[3];
    const float* m1           = (const float*)d_in[4];
    float*       out          = (float*)d_out;

    int n = in_sizes[0] / 3;   // N_QUERIES

    pack_offsets_kernel<<<(OFF_N + 255) / 256, 256>>>(offset_table);

    long long threads_needed = ((long long)n + QPT - 1) / QPT;
    int blocks = (int)((threads_needed + 255) / 256);
    psh_kernel<<<blocks, 256>>>(coords, hash_table, m0, m1, out, n);
}